// round 14
// baseline (speedup 1.0000x reference)
#include <cuda_runtime.h>
#include <cuda_fp16.h>
#include <math.h>
#include <cstdint>

#define BB   4
#define NN   512
#define CIN  128
#define CMID 64

// ------------------------- scratch (device globals) ------------------------
__device__ __half g_h[(size_t)BB * NN * NN * CMID];  // upper-triangle h (fp16)
__device__ float g_A[(size_t)BB * NN * NN];          // 4 MB softmax probs
__device__ float g_u[BB * NN * CMID];                // u = x@W1^T + b1/2
__device__ __half g_x16[BB * NN * CIN];              // fp16 copy of x
__device__ uint32_t g_whi[64 * 64];                  // W1 hi fp16x2 [o][kp]
__device__ uint32_t g_wlo[64 * 64];                  // W1 lo fp16x2
__device__ float g_stats[32 * 128];
__device__ float g_y0p[8 * BB * NN * CIN];           // y0 partials (8 j-slices)
__device__ float g_y1[BB * NN * 128];
__device__ float g_statsg[2 * 128];

// ------------------------- PTX helpers -------------------------------------
__device__ __forceinline__ void mma_f16(float* d, const uint32_t* a,
                                        uint32_t b0, uint32_t b1) {
    asm volatile(
        "mma.sync.aligned.m16n8k16.row.col.f32.f16.f16.f32 "
        "{%0,%1,%2,%3}, {%4,%5,%6,%7}, {%8,%9}, {%0,%1,%2,%3};"
        : "+f"(d[0]), "+f"(d[1]), "+f"(d[2]), "+f"(d[3])
        : "r"(a[0]), "r"(a[1]), "r"(a[2]), "r"(a[3]), "r"(b0), "r"(b1));
}
__device__ __forceinline__ void ldsm_x4(uint32_t &r0, uint32_t &r1,
                                        uint32_t &r2, uint32_t &r3, uint32_t addr) {
    asm volatile("ldmatrix.sync.aligned.m8n8.x4.shared.b16 {%0,%1,%2,%3}, [%4];"
                 : "=r"(r0), "=r"(r1), "=r"(r2), "=r"(r3) : "r"(addr));
}
__device__ __forceinline__ uint32_t hmin2u(uint32_t a, uint32_t b) {
    __half2 r = __hmin2(*reinterpret_cast<__half2*>(&a), *reinterpret_cast<__half2*>(&b));
    return *reinterpret_cast<uint32_t*>(&r);
}

// ------------------------- Kinit: cvt + W split + u-GEMM + zero stats -----
__global__ __launch_bounds__(256) void k_init(const float* __restrict__ x,
                                              const float* __restrict__ W1,
                                              const float* __restrict__ b1) {
    __shared__ float xr[16][128];
    __shared__ float Ws[128 * 64];
    const int tid = threadIdx.x;
    const int blk = blockIdx.x;

    if (blk < 512) {
        int idx = blk * 256 + tid;
        float2 v = *(const float2*)&x[idx * 2];
        uint32_t p;
        asm("cvt.rn.f16x2.f32 %0, %1, %2;" : "=r"(p) : "f"(v.y), "f"(v.x));
        ((uint32_t*)g_x16)[idx] = p;

        if (blk < 16) {
            int i2 = blk * 256 + tid;
            float2 wv = *(const float2*)&W1[i2 * 2];
            uint32_t hp;
            asm("cvt.rn.f16x2.f32 %0, %1, %2;" : "=r"(hp) : "f"(wv.y), "f"(wv.x));
            __half2 hh = *reinterpret_cast<__half2*>(&hp);
            float2 hf = __half22float2(hh);
            uint32_t lp;
            asm("cvt.rn.f16x2.f32 %0, %1, %2;" : "=r"(lp) : "f"(wv.y - hf.y), "f"(wv.x - hf.x));
            g_whi[i2] = hp;
            g_wlo[i2] = lp;
        }
        if (blk == 511) {
            for (int i = tid; i < 32 * 128; i += 256) g_stats[i] = 0.f;
            g_statsg[tid] = 0.f;
        }
        return;
    }

    const int r0 = (blk - 512) * 16;
    for (int idx = tid; idx < 64 * 128; idx += 256)
        Ws[(idx & 127) * 64 + (idx >> 7)] = W1[idx];
    for (int idx = tid; idx < 16 * 128; idx += 256)
        xr[idx >> 7][idx & 127] = x[(size_t)(r0 + (idx >> 7)) * 128 + (idx & 127)];
    __syncthreads();
    const int row = tid >> 4, chg = (tid & 15) * 4;
    float acc[4];
#pragma unroll
    for (int c = 0; c < 4; c++) acc[c] = 0.5f * b1[chg + c];
    for (int k = 0; k < 128; k++) {
        float xv = xr[row][k];
#pragma unroll
        for (int c = 0; c < 4; c++) acc[c] += Ws[k * 64 + chg + c] * xv;
    }
#pragma unroll
    for (int c = 0; c < 4; c++)
        g_u[(size_t)(r0 + row) * CMID + chg + c] = acc[c];
}

// ------------------------- K1: symmetric pairwise GEMM (2 i / block) ------
// stores ONLY j >= i (upper triangle); k3 reads transposed for j < i.
#define OFF_XIP  0
#define OFF_SRED 512
#define OFF_XJ   4608
#define OFF_WHI  39424
#define OFF_WLO  56832
#define K1_SMEM  74240

__global__ __launch_bounds__(256) void k1_pair_gemm() {
    const int jt = blockIdx.x, iy = blockIdx.y, b = blockIdx.z;
    const int i0 = iy * 2;
    if (jt < (i0 >> 7)) return;

    extern __shared__ char smem[];
    uint32_t* xiP  = (uint32_t*)(smem + OFF_XIP);
    float*    sred = (float*)(smem + OFF_SRED);
    uint32_t* xjs  = (uint32_t*)(smem + OFF_XJ);
    uint32_t* whiS = (uint32_t*)(smem + OFF_WHI);
    uint32_t* wloS = (uint32_t*)(smem + OFF_WLO);

    const uint32_t sb = (uint32_t)__cvta_generic_to_shared(smem);
    const uint32_t xj_b  = sb + OFF_XJ;
    const uint32_t whi_b = sb + OFF_WHI;
    const uint32_t wlo_b = sb + OFF_WLO;

    const int tid = threadIdx.x;
    const int hf = tid >> 7;
    const int wg = tid & 127;
    const int w = wg >> 5, l = wg & 31;
    const int lr = l >> 2, lc = l & 3;
    const int i = i0 + hf;
    const int j0 = jt * 128;
    const size_t bOff = (size_t)b * NN;
    const uint32_t* x16u = (const uint32_t*)g_x16;

    if (tid < 128) xiP[tid] = x16u[(bOff + i0 + (tid >> 6)) * 64 + (tid & 63)];
    for (int idx = tid; idx < 128 * 64; idx += 256) {
        int row = idx >> 6, col = idx & 63;
        xjs[row * 68 + col] = x16u[(bOff + j0 + row) * 64 + col];
    }
    for (int idx = tid; idx < 64 * 64; idx += 256) {
        int o = idx >> 6, kp = idx & 63;
        whiS[o * 68 + kp] = g_whi[idx];
        wloS[o * 68 + kp] = g_wlo[idx];
    }
    __syncthreads();

    uint32_t xvlo[8], xvhi[8];
#pragma unroll
    for (int s = 0; s < 8; s++) {
        xvlo[s] = xiP[hf * 64 + s * 8 + lc];
        xvhi[s] = xiP[hf * 64 + s * 8 + 4 + lc];
    }

    uint32_t ofsA[2], ofsW[4];
#pragma unroll
    for (int mt = 0; mt < 2; mt++) {
        int rowA = w * 32 + mt * 16 + (l & 15);
        ofsA[mt] = (uint32_t)((rowA * 68 + ((l >> 4) << 2)) * 4);
    }
#pragma unroll
    for (int q = 0; q < 4; q++) {
        int rowW = 16 * q + ((l >> 4) << 3) + (l & 7);
        int woff = ((l >> 3) & 1) << 2;
        ofsW[q] = (uint32_t)((rowW * 68 + woff) * 4);
    }

    float d[2][8][4];
#pragma unroll
    for (int mt = 0; mt < 2; mt++)
#pragma unroll
        for (int nt = 0; nt < 8; nt++)
#pragma unroll
            for (int r = 0; r < 4; r++) d[mt][nt][r] = 0.f;

#pragma unroll
    for (int s = 0; s < 8; s++) {
        const uint32_t kb = (uint32_t)(s * 32);
        uint32_t a[2][4];
#pragma unroll
        for (int mt = 0; mt < 2; mt++) {
            uint32_t r0, r1, r2, r3;
            ldsm_x4(r0, r1, r2, r3, xj_b + ofsA[mt] + kb);
            a[mt][0] = hmin2u(r0, xvlo[s]);
            a[mt][1] = hmin2u(r1, xvlo[s]);
            a[mt][2] = hmin2u(r2, xvhi[s]);
            a[mt][3] = hmin2u(r3, xvhi[s]);
        }
#pragma unroll
        for (int q = 0; q < 4; q++) {
            uint32_t h0, h1, h2, h3, l0, l1, l2, l3;
            ldsm_x4(h0, h1, h2, h3, whi_b + ofsW[q] + kb);
            ldsm_x4(l0, l1, l2, l3, wlo_b + ofsW[q] + kb);
            mma_f16(d[0][2 * q],     a[0], h0, h1);
            mma_f16(d[0][2 * q + 1], a[0], h2, h3);
            mma_f16(d[1][2 * q],     a[1], h0, h1);
            mma_f16(d[1][2 * q + 1], a[1], h2, h3);
            mma_f16(d[0][2 * q],     a[0], l0, l1);
            mma_f16(d[0][2 * q + 1], a[0], l2, l3);
            mma_f16(d[1][2 * q],     a[1], l0, l1);
            mma_f16(d[1][2 * q + 1], a[1], l2, l3);
        }
    }
    __syncthreads();

    uint32_t* Dsm = (hf == 0) ? xjs : whiS;
    float ssum[16], ssq[16];
#pragma unroll
    for (int s = 0; s < 16; s++) { ssum[s] = 0.f; ssq[s] = 0.f; }

    const float* uB = g_u + bOff * CMID;
    float uI[16];
#pragma unroll
    for (int nt = 0; nt < 8; nt++) {
        float2 t = *(const float2*)&uB[(size_t)i * CMID + nt * 8 + lc * 2];
        uI[nt * 2] = t.x; uI[nt * 2 + 1] = t.y;
    }

#pragma unroll
    for (int mt = 0; mt < 2; mt++) {
        const int row0 = w * 32 + mt * 16 + lr;
        const int row1 = row0 + 8;
        const int jrow0 = j0 + row0, jrow1 = j0 + row1;
        const float w0f = (jrow0 > i) ? 2.f : (jrow0 == i ? 1.f : 0.f);
        const float w1f = (jrow1 > i) ? 2.f : (jrow1 == i ? 1.f : 0.f);
        const float* uj0p = &uB[(size_t)jrow0 * CMID];
        const float* uj1p = &uB[(size_t)jrow1 * CMID];
#pragma unroll
        for (int nt = 0; nt < 8; nt++) {
            const int ch = nt * 8 + lc * 2;
            float2 uj0 = *(const float2*)&uj0p[ch];
            float2 uj1 = *(const float2*)&uj1p[ch];
            float v0 = uI[nt * 2]     + uj0.x - 2.f * d[mt][nt][0];
            float v1 = uI[nt * 2 + 1] + uj0.y - 2.f * d[mt][nt][1];
            float v2 = uI[nt * 2]     + uj1.x - 2.f * d[mt][nt][2];
            float v3 = uI[nt * 2 + 1] + uj1.y - 2.f * d[mt][nt][3];
            uint32_t p01, p23;
            asm("cvt.rn.f16x2.f32 %0, %1, %2;" : "=r"(p01) : "f"(v1), "f"(v0));
            asm("cvt.rn.f16x2.f32 %0, %1, %2;" : "=r"(p23) : "f"(v3), "f"(v2));
            Dsm[row0 * 36 + nt * 4 + lc] = p01;
            Dsm[row1 * 36 + nt * 4 + lc] = p23;
            ssum[nt * 2]     += w0f * v0 + w1f * v2;
            ssq[nt * 2]      += w0f * v0 * v0 + w1f * v2 * v2;
            ssum[nt * 2 + 1] += w0f * v1 + w1f * v3;
            ssq[nt * 2 + 1]  += w0f * v1 * v1 + w1f * v3 * v3;
        }
    }
#pragma unroll
    for (int s = 0; s < 16; s++) {
#pragma unroll
        for (int off = 4; off <= 16; off <<= 1) {
            ssum[s] += __shfl_xor_sync(0xffffffffu, ssum[s], off);
            ssq[s]  += __shfl_xor_sync(0xffffffffu, ssq[s], off);
        }
    }
    const int warp8 = tid >> 5;
    if (l < 4) {
#pragma unroll
        for (int nt = 0; nt < 8; nt++) {
            sred[warp8 * 128 + nt * 8 + l * 2]          = ssum[nt * 2];
            sred[warp8 * 128 + nt * 8 + l * 2 + 1]      = ssum[nt * 2 + 1];
            sred[warp8 * 128 + 64 + nt * 8 + l * 2]     = ssq[nt * 2];
            sred[warp8 * 128 + 64 + nt * 8 + l * 2 + 1] = ssq[nt * 2 + 1];
        }
    }
    __syncthreads();
    if (tid < 128) {
        float a = 0.f;
#pragma unroll
        for (int ww = 0; ww < 8; ww++) a += sred[ww * 128 + tid];
        int slot = (blockIdx.x + (blockIdx.y << 2) + blockIdx.z) & 31;
        atomicAdd(&g_stats[slot * 128 + tid], a);
    }

    // coalesced stores: upper triangle only (no mirror)
    {
        __half* hdir = g_h + ((bOff + i) * NN + j0) * CMID;
#pragma unroll
        for (int t = 0; t < 8; t++) {
            int flat = t * 128 + wg;
            int row = flat >> 3, c = flat & 7;
            if (j0 + row >= i) {
                uint4 v = *(uint4*)&Dsm[row * 36 + c * 4];
                *(uint4*)&hdir[(size_t)row * CMID + c * 8] = v;
            }
        }
    }
}

// ------------------------- K3: BN finalize + scores + softmax -> g_A ------
// h read via triangle addressing: element (i,j) lives at (min,max).
__global__ __launch_bounds__(256) void k3_softmax(const int* __restrict__ A_init,
                                                  const float* __restrict__ W2,
                                                  const float* __restrict__ b2,
                                                  const float* __restrict__ g1,
                                                  const float* __restrict__ be1) {
    __shared__ float sA[512];
    __shared__ float saf[64], scf[64];
    __shared__ __half2 sa2[32], sc2[32], sw2[32];
    __shared__ float red[16];

    const int tid = threadIdx.x;
    const int i = blockIdx.x, b = blockIdx.y;
    if (tid < 64) {
        float s = 0.f, q = 0.f;
#pragma unroll
        for (int sl = 0; sl < 32; sl++) {
            s += g_stats[sl * 128 + tid];
            q += g_stats[sl * 128 + 64 + tid];
        }
        const float invcnt = 1.0f / (float)((size_t)BB * NN * NN);
        float m = s * invcnt;
        float v = q * invcnt - m * m;
        float a = g1[tid] / sqrtf(v + 1e-5f);
        saf[tid] = a;
        scf[tid] = be1[tid] - m * a;
    }
    __syncthreads();
    if (tid < 32) {
        sa2[tid] = __floats2half2_rn(saf[2 * tid], saf[2 * tid + 1]);
        sc2[tid] = __floats2half2_rn(scf[2 * tid], scf[2 * tid + 1]);
        sw2[tid] = __floats2half2_rn(W2[2 * tid], W2[2 * tid + 1]);
    }
    __syncthreads();

    const int w = tid >> 5, l = tid & 31, g2 = l >> 3, q = l & 7;
    const __half* hb = g_h + (size_t)b * NN * NN * CMID;
    const int* arow = A_init + ((size_t)b * NN + i) * NN;
    const float b2v = b2[0];
    __half2 a2[4], c2[4], w2[4];
#pragma unroll
    for (int k = 0; k < 4; k++) {
        a2[k] = sa2[q * 4 + k];
        c2[k] = sc2[q * 4 + k];
        w2[k] = sw2[q * 4 + k];
    }
    const __half2 zero2 = __floats2half2_rn(0.f, 0.f);
    const __half2 leak2 = __floats2half2_rn(0.01f, 0.01f);
    const int o = q * 8;

#pragma unroll 4
    for (int t = 0; t < 16; t++) {
        int j = t * 32 + w * 4 + g2;
        size_t off = (j >= i) ? ((size_t)i * NN + j) : ((size_t)j * NN + i);
        uint4 raw = *(const uint4*)(hb + off * CMID + o);
        const __half2* hp = (const __half2*)&raw;
        __half2 p2 = zero2;
#pragma unroll
        for (int k = 0; k < 4; k++) {
            __half2 z = __hfma2(hp[k], a2[k], c2[k]);
            __half2 zp = __hmax2(z, zero2);
            __half2 zn = __hmin2(z, zero2);
            z = __hfma2(zn, leak2, zp);
            p2 = __hfma2(z, w2[k], p2);
        }
        float2 pf = __half22float2(p2);
        float p = pf.x + pf.y;
        p += __shfl_down_sync(0xffffffffu, p, 4, 8);
        p += __shfl_down_sync(0xffffffffu, p, 2, 8);
        p += __shfl_down_sync(0xffffffffu, p, 1, 8);
        if (q == 0) sA[j] = (arow[j] > 0) ? (p + b2v) : -9e15f;
    }
    __syncthreads();

    float m0 = fmaxf(sA[tid], sA[tid + 256]);
#pragma unroll
    for (int off = 16; off > 0; off >>= 1) m0 = fmaxf(m0, __shfl_xor_sync(0xffffffffu, m0, off));
    if (l == 0) red[w] = m0;
    __syncthreads();
    float m = red[0];
#pragma unroll
    for (int k = 1; k < 8; k++) m = fmaxf(m, red[k]);

    float e0 = __expf(sA[tid] - m), e1 = __expf(sA[tid + 256] - m);
    float ps = e0 + e1;
#pragma unroll
    for (int off = 16; off > 0; off >>= 1) ps += __shfl_xor_sync(0xffffffffu, ps, off);
    if (l == 0) red[8 + w] = ps;
    __syncthreads();
    float tot = red[8] + red[9] + red[10] + red[11] + red[12] + red[13] + red[14] + red[15];
    float inv = 1.0f / tot;

    const size_t rowbase = ((size_t)b * NN + i) * NN;
    g_A[rowbase + tid]       = e0 * inv;
    g_A[rowbase + 256 + tid] = e1 * inv;
}

// ------------------------- K3b: y0 partials = A[:,js] @ x[js] -------------
__global__ __launch_bounds__(256) void k3b_agg(const float* __restrict__ x) {
    __shared__ float xs[64][128];
    __shared__ float as[32][64];
    const int tid = threadIdx.x;
    const int it = blockIdx.x, js = blockIdx.y, b = blockIdx.z;
    const int i0 = it * 32;
    const int jbase = js * 64;
    const int c = tid & 127, half = tid >> 7;

    for (int idx = tid * 4; idx < 64 * 128; idx += 256 * 4) {
        int r = idx >> 7, cc = idx & 127;
        *(float4*)&xs[r][cc] =
            *(const float4*)&x[((size_t)b * NN + jbase + r) * CIN + cc];
    }
    for (int idx = tid * 4; idx < 32 * 64; idx += 256 * 4) {
        int r = idx >> 6, j = idx & 63;
        *(float4*)&as[r][j] =
            __ldcs((const float4*)&g_A[((size_t)b * NN + i0 + r) * NN + jbase + j]);
    }
    __syncthreads();

    float acc[16];
#pragma unroll
    for (int r = 0; r < 16; r++) acc[r] = 0.f;

    for (int j = 0; j < 64; j += 4) {
        float x0 = xs[j][c], x1 = xs[j + 1][c], x2 = xs[j + 2][c], x3 = xs[j + 3][c];
#pragma unroll
        for (int r = 0; r < 16; r++) {
            float4 a4 = *(const float4*)&as[half * 16 + r][j];
            acc[r] += a4.x * x0 + a4.y * x1 + a4.z * x2 + a4.w * x3;
        }
    }
    float* dst = g_y0p + (size_t)js * BB * NN * CIN;
#pragma unroll
    for (int r = 0; r < 16; r++)
        dst[((size_t)b * NN + i0 + half * 16 + r) * CIN + c] = acc[r];
}

// ------------------------- K4: y1 = y0 @ Wg^T + bg, + BN1d stats ----------
__global__ __launch_bounds__(256) void k4_fc_g(const float* __restrict__ Wg,
                                               const float* __restrict__ bg) {
    __shared__ float ys[16][129];
    __shared__ float s0[128], q0[128];
    const int tid = threadIdx.x;
    const int rb = blockIdx.x;
    const int stride = BB * NN * CIN;
    for (int idx = tid; idx < 16 * 128; idx += 256) {
        int r = idx >> 7, c = idx & 127;
        size_t base = (size_t)(rb * 16 + r) * 128 + c;
        float s = 0.f;
#pragma unroll
        for (int p = 0; p < 8; p++) s += g_y0p[base + (size_t)p * stride];
        ys[r][c] = s;
    }
    __syncthreads();
    const int c = tid & 127, half = tid >> 7;
    float acc[8];
    const float bgv = bg[c];
#pragma unroll
    for (int r = 0; r < 8; r++) acc[r] = bgv;
    const float* wrow = Wg + (size_t)c * 128;
    for (int k = 0; k < 128; k++) {
        float w = __ldg(&wrow[k]);
#pragma unroll
        for (int r = 0; r < 8; r++) acc[r] += ys[half * 8 + r][k] * w;
    }
    float s = 0.f, q = 0.f;
#pragma unroll
    for (int r = 0; r < 8; r++) {
        float v = acc[r];
        s += v; q += v * v;
        g_y1[(size_t)(rb * 16 + half * 8 + r) * 128 + c] = v;
    }
    if (half == 0) { s0[c] = s; q0[c] = q; }
    __syncthreads();
    if (half == 1) {
        atomicAdd(&g_statsg[c], s + s0[c]);
        atomicAdd(&g_statsg[128 + c], q + q0[c]);
    }
}

// ------------------------- K6: BN1d finalize + out GEMM -------------------
__global__ __launch_bounds__(256) void k6_trans(const float* __restrict__ x,
                                                const float* __restrict__ Wt,
                                                const float* __restrict__ bt,
                                                const float* __restrict__ gg,
                                                const float* __restrict__ beg,
                                                float* __restrict__ out) {
    __shared__ float zs[16][257];
    __shared__ float bna[128], bnc[128];
    const int tid = threadIdx.x;
    const int rb = blockIdx.x;
    if (tid < 128) {
        const float invcnt = 1.0f / (float)(BB * NN);
        float m = g_statsg[tid] * invcnt;
        float v = g_statsg[128 + tid] * invcnt - m * m;
        float a = gg[tid] / sqrtf(v + 1e-5f);
        bna[tid] = a;
        bnc[tid] = beg[tid] - m * a;
    }
    __syncthreads();
    for (int idx = tid; idx < 16 * 256; idx += 256) {
        int r = idx >> 8, k = idx & 255;
        int row = rb * 16 + r;
        float v;
        if (k < 128) {
            v = x[(size_t)row * 128 + k];
        } else {
            int hch = k - 128;
            float y = g_y1[(size_t)row * 128 + hch];
            y = y * bna[hch] + bnc[hch];
            v = y > 0.f ? y : 0.01f * y;
        }
        zs[r][k] = v;
    }
    __syncthreads();
    const int c = tid & 127, half = tid >> 7;
    float acc[8];
    const float btv = bt[c];
#pragma unroll
    for (int r = 0; r < 8; r++) acc[r] = btv;
    const float* wrow = Wt + (size_t)c * 256;
    for (int k = 0; k < 256; k++) {
        float w = __ldg(&wrow[k]);
#pragma unroll
        for (int r = 0; r < 8; r++) acc[r] += zs[half * 8 + r][k] * w;
    }
#pragma unroll
    for (int r = 0; r < 8; r++)
        out[(size_t)(rb * 16 + half * 8 + r) * 128 + c] = acc[r];
}

// ------------------------- launch -----------------------------------------
extern "C" void kernel_launch(void* const* d_in, const int* in_sizes, int n_in,
                              void* d_out, int out_size) {
    const float* x      = (const float*)d_in[0];
    const int*   A_init = (const int*)d_in[1];
    const float* W1     = (const float*)d_in[2];
    const float* b1     = (const float*)d_in[3];
    const float* g1     = (const float*)d_in[4];
    const float* be1    = (const float*)d_in[5];
    const float* W2     = (const float*)d_in[6];
    const float* b2     = (const float*)d_in[7];
    const float* Wg     = (const float*)d_in[8];
    const float* bg     = (const float*)d_in[9];
    const float* gg     = (const float*)d_in[10];
    const float* beg    = (const float*)d_in[11];
    const float* Wt     = (const float*)d_in[12];
    const float* bt     = (const float*)d_in[13];
    float* out = (float*)d_out;

    cudaFuncSetAttribute(k1_pair_gemm, cudaFuncAttributeMaxDynamicSharedMemorySize, K1_SMEM);

    k_init<<<640, 256>>>(x, W1, b1);
    dim3 g1grid(4, 256, 4);
    k1_pair_gemm<<<g1grid, 256, K1_SMEM>>>();
    dim3 g3grid(512, 4);
    k3_softmax<<<g3grid, 256>>>(A_init, W2, b2, g1, be1);
    dim3 g3bgrid(16, 8, 4);
    k3b_agg<<<g3bgrid, 256>>>(x);
    k4_fc_g<<<128, 256>>>(Wg, bg);
    k6_trans<<<128, 256>>>(x, Wt, bt, gg, beg, out);
}

// round 15
// speedup vs baseline: 1.4110x; 1.4110x over previous
#include <cuda_runtime.h>
#include <cuda_fp16.h>
#include <math.h>
#include <cstdint>

#define BB   4
#define NN   512
#define CIN  128
#define CMID 64

// ------------------------- scratch (device globals) ------------------------
__device__ __half g_h[(size_t)BB * NN * NN * CMID];  // 128 MB h (fp16)
__device__ float g_A[(size_t)BB * NN * NN];          // 4 MB softmax probs
__device__ float g_u[BB * NN * CMID];                // u = x@W1^T + b1/2
__device__ __half g_x16[BB * NN * CIN];              // fp16 copy of x
__device__ uint32_t g_whi[64 * 64];                  // W1 hi fp16x2 [o][kp]
__device__ uint32_t g_wlo[64 * 64];                  // W1 lo fp16x2
__device__ float g_stats[32 * 128];
__device__ float g_y0p[8 * BB * NN * CIN];           // y0 partials (8 j-slices)
__device__ float g_y1[BB * NN * 128];
__device__ float g_statsg[2 * 128];

// ------------------------- PTX helpers -------------------------------------
__device__ __forceinline__ void mma_f16(float* d, const uint32_t* a,
                                        uint32_t b0, uint32_t b1) {
    asm volatile(
        "mma.sync.aligned.m16n8k16.row.col.f32.f16.f16.f32 "
        "{%0,%1,%2,%3}, {%4,%5,%6,%7}, {%8,%9}, {%0,%1,%2,%3};"
        : "+f"(d[0]), "+f"(d[1]), "+f"(d[2]), "+f"(d[3])
        : "r"(a[0]), "r"(a[1]), "r"(a[2]), "r"(a[3]), "r"(b0), "r"(b1));
}
__device__ __forceinline__ void ldsm_x4(uint32_t &r0, uint32_t &r1,
                                        uint32_t &r2, uint32_t &r3, uint32_t addr) {
    asm volatile("ldmatrix.sync.aligned.m8n8.x4.shared.b16 {%0,%1,%2,%3}, [%4];"
                 : "=r"(r0), "=r"(r1), "=r"(r2), "=r"(r3) : "r"(addr));
}
__device__ __forceinline__ uint32_t hmin2u(uint32_t a, uint32_t b) {
    __half2 r = __hmin2(*reinterpret_cast<__half2*>(&a), *reinterpret_cast<__half2*>(&b));
    return *reinterpret_cast<uint32_t*>(&r);
}

// ------------------------- Kinit: cvt + W split + u-GEMM + zero stats -----
__global__ __launch_bounds__(256) void k_init(const float* __restrict__ x,
                                              const float* __restrict__ W1,
                                              const float* __restrict__ b1) {
    __shared__ float xr[16][128];
    __shared__ float Ws[128 * 64];
    const int tid = threadIdx.x;
    const int blk = blockIdx.x;

    if (blk < 512) {
        int idx = blk * 256 + tid;
        float2 v = *(const float2*)&x[idx * 2];
        uint32_t p;
        asm("cvt.rn.f16x2.f32 %0, %1, %2;" : "=r"(p) : "f"(v.y), "f"(v.x));
        ((uint32_t*)g_x16)[idx] = p;

        if (blk < 16) {
            int i2 = blk * 256 + tid;
            float2 wv = *(const float2*)&W1[i2 * 2];
            uint32_t hp;
            asm("cvt.rn.f16x2.f32 %0, %1, %2;" : "=r"(hp) : "f"(wv.y), "f"(wv.x));
            __half2 hh = *reinterpret_cast<__half2*>(&hp);
            float2 hf = __half22float2(hh);
            uint32_t lp;
            asm("cvt.rn.f16x2.f32 %0, %1, %2;" : "=r"(lp) : "f"(wv.y - hf.y), "f"(wv.x - hf.x));
            g_whi[i2] = hp;
            g_wlo[i2] = lp;
        }
        if (blk == 511) {
            for (int i = tid; i < 32 * 128; i += 256) g_stats[i] = 0.f;
            g_statsg[tid] = 0.f;
        }
        return;
    }

    const int r0 = (blk - 512) * 16;
    for (int idx = tid; idx < 64 * 128; idx += 256)
        Ws[(idx & 127) * 64 + (idx >> 7)] = W1[idx];
    for (int idx = tid; idx < 16 * 128; idx += 256)
        xr[idx >> 7][idx & 127] = x[(size_t)(r0 + (idx >> 7)) * 128 + (idx & 127)];
    __syncthreads();
    const int row = tid >> 4, chg = (tid & 15) * 4;
    float acc[4];
#pragma unroll
    for (int c = 0; c < 4; c++) acc[c] = 0.5f * b1[chg + c];
    for (int k = 0; k < 128; k++) {
        float xv = xr[row][k];
#pragma unroll
        for (int c = 0; c < 4; c++) acc[c] += Ws[k * 64 + chg + c] * xv;
    }
#pragma unroll
    for (int c = 0; c < 4; c++)
        g_u[(size_t)(r0 + row) * CMID + chg + c] = acc[c];
}

// ------------------------- K1: symmetric pairwise GEMM (2 i / block) ------
#define OFF_XIP  0
#define OFF_SRED 512
#define OFF_XJ   4608
#define OFF_WHI  39424
#define OFF_WLO  56832
#define K1_SMEM  74240

__global__ __launch_bounds__(256) void k1_pair_gemm() {
    const int jt = blockIdx.x, iy = blockIdx.y, b = blockIdx.z;
    const int i0 = iy * 2;
    if (jt < (i0 >> 7)) return;

    extern __shared__ char smem[];
    uint32_t* xiP  = (uint32_t*)(smem + OFF_XIP);
    float*    sred = (float*)(smem + OFF_SRED);
    uint32_t* xjs  = (uint32_t*)(smem + OFF_XJ);
    uint32_t* whiS = (uint32_t*)(smem + OFF_WHI);
    uint32_t* wloS = (uint32_t*)(smem + OFF_WLO);

    const uint32_t sb = (uint32_t)__cvta_generic_to_shared(smem);
    const uint32_t xj_b  = sb + OFF_XJ;
    const uint32_t whi_b = sb + OFF_WHI;
    const uint32_t wlo_b = sb + OFF_WLO;

    const int tid = threadIdx.x;
    const int hf = tid >> 7;
    const int wg = tid & 127;
    const int w = wg >> 5, l = wg & 31;
    const int lr = l >> 2, lc = l & 3;
    const int i = i0 + hf;
    const int j0 = jt * 128;
    const size_t bOff = (size_t)b * NN;
    const uint32_t* x16u = (const uint32_t*)g_x16;

    if (tid < 128) xiP[tid] = x16u[(bOff + i0 + (tid >> 6)) * 64 + (tid & 63)];
    for (int idx = tid; idx < 128 * 64; idx += 256) {
        int row = idx >> 6, col = idx & 63;
        xjs[row * 68 + col] = x16u[(bOff + j0 + row) * 64 + col];
    }
    for (int idx = tid; idx < 64 * 64; idx += 256) {
        int o = idx >> 6, kp = idx & 63;
        whiS[o * 68 + kp] = g_whi[idx];
        wloS[o * 68 + kp] = g_wlo[idx];
    }
    __syncthreads();

    uint32_t xvlo[8], xvhi[8];
#pragma unroll
    for (int s = 0; s < 8; s++) {
        xvlo[s] = xiP[hf * 64 + s * 8 + lc];
        xvhi[s] = xiP[hf * 64 + s * 8 + 4 + lc];
    }

    uint32_t ofsA[2], ofsW[4];
#pragma unroll
    for (int mt = 0; mt < 2; mt++) {
        int rowA = w * 32 + mt * 16 + (l & 15);
        ofsA[mt] = (uint32_t)((rowA * 68 + ((l >> 4) << 2)) * 4);
    }
#pragma unroll
    for (int q = 0; q < 4; q++) {
        int rowW = 16 * q + ((l >> 4) << 3) + (l & 7);
        int woff = ((l >> 3) & 1) << 2;
        ofsW[q] = (uint32_t)((rowW * 68 + woff) * 4);
    }

    float d[2][8][4];
#pragma unroll
    for (int mt = 0; mt < 2; mt++)
#pragma unroll
        for (int nt = 0; nt < 8; nt++)
#pragma unroll
            for (int r = 0; r < 4; r++) d[mt][nt][r] = 0.f;

#pragma unroll
    for (int s = 0; s < 8; s++) {
        const uint32_t kb = (uint32_t)(s * 32);
        uint32_t a[2][4];
#pragma unroll
        for (int mt = 0; mt < 2; mt++) {
            uint32_t r0, r1, r2, r3;
            ldsm_x4(r0, r1, r2, r3, xj_b + ofsA[mt] + kb);
            a[mt][0] = hmin2u(r0, xvlo[s]);
            a[mt][1] = hmin2u(r1, xvlo[s]);
            a[mt][2] = hmin2u(r2, xvhi[s]);
            a[mt][3] = hmin2u(r3, xvhi[s]);
        }
#pragma unroll
        for (int q = 0; q < 4; q++) {
            uint32_t h0, h1, h2, h3, l0, l1, l2, l3;
            ldsm_x4(h0, h1, h2, h3, whi_b + ofsW[q] + kb);
            ldsm_x4(l0, l1, l2, l3, wlo_b + ofsW[q] + kb);
            mma_f16(d[0][2 * q],     a[0], h0, h1);
            mma_f16(d[0][2 * q + 1], a[0], h2, h3);
            mma_f16(d[1][2 * q],     a[1], h0, h1);
            mma_f16(d[1][2 * q + 1], a[1], h2, h3);
            mma_f16(d[0][2 * q],     a[0], l0, l1);
            mma_f16(d[0][2 * q + 1], a[0], l2, l3);
            mma_f16(d[1][2 * q],     a[1], l0, l1);
            mma_f16(d[1][2 * q + 1], a[1], l2, l3);
        }
    }
    __syncthreads();

    uint32_t* Dsm = (hf == 0) ? xjs : whiS;
    float ssum[16], ssq[16];
#pragma unroll
    for (int s = 0; s < 16; s++) { ssum[s] = 0.f; ssq[s] = 0.f; }

    const float* uB = g_u + bOff * CMID;
    float uI[16];
#pragma unroll
    for (int nt = 0; nt < 8; nt++) {
        float2 t = *(const float2*)&uB[(size_t)i * CMID + nt * 8 + lc * 2];
        uI[nt * 2] = t.x; uI[nt * 2 + 1] = t.y;
    }

#pragma unroll
    for (int mt = 0; mt < 2; mt++) {
        const int row0 = w * 32 + mt * 16 + lr;
        const int row1 = row0 + 8;
        const int jrow0 = j0 + row0, jrow1 = j0 + row1;
        const float w0f = (jrow0 > i) ? 2.f : (jrow0 == i ? 1.f : 0.f);
        const float w1f = (jrow1 > i) ? 2.f : (jrow1 == i ? 1.f : 0.f);
        const float* uj0p = &uB[(size_t)jrow0 * CMID];
        const float* uj1p = &uB[(size_t)jrow1 * CMID];
#pragma unroll
        for (int nt = 0; nt < 8; nt++) {
            const int ch = nt * 8 + lc * 2;
            float2 uj0 = *(const float2*)&uj0p[ch];
            float2 uj1 = *(const float2*)&uj1p[ch];
            float v0 = uI[nt * 2]     + uj0.x - 2.f * d[mt][nt][0];
            float v1 = uI[nt * 2 + 1] + uj0.y - 2.f * d[mt][nt][1];
            float v2 = uI[nt * 2]     + uj1.x - 2.f * d[mt][nt][2];
            float v3 = uI[nt * 2 + 1] + uj1.y - 2.f * d[mt][nt][3];
            uint32_t p01, p23;
            asm("cvt.rn.f16x2.f32 %0, %1, %2;" : "=r"(p01) : "f"(v1), "f"(v0));
            asm("cvt.rn.f16x2.f32 %0, %1, %2;" : "=r"(p23) : "f"(v3), "f"(v2));
            Dsm[row0 * 36 + nt * 4 + lc] = p01;
            Dsm[row1 * 36 + nt * 4 + lc] = p23;
            ssum[nt * 2]     += w0f * v0 + w1f * v2;
            ssq[nt * 2]      += w0f * v0 * v0 + w1f * v2 * v2;
            ssum[nt * 2 + 1] += w0f * v1 + w1f * v3;
            ssq[nt * 2 + 1]  += w0f * v1 * v1 + w1f * v3 * v3;
        }
    }
#pragma unroll
    for (int s = 0; s < 16; s++) {
#pragma unroll
        for (int off = 4; off <= 16; off <<= 1) {
            ssum[s] += __shfl_xor_sync(0xffffffffu, ssum[s], off);
            ssq[s]  += __shfl_xor_sync(0xffffffffu, ssq[s], off);
        }
    }
    const int warp8 = tid >> 5;
    if (l < 4) {
#pragma unroll
        for (int nt = 0; nt < 8; nt++) {
            sred[warp8 * 128 + nt * 8 + l * 2]          = ssum[nt * 2];
            sred[warp8 * 128 + nt * 8 + l * 2 + 1]      = ssum[nt * 2 + 1];
            sred[warp8 * 128 + 64 + nt * 8 + l * 2]     = ssq[nt * 2];
            sred[warp8 * 128 + 64 + nt * 8 + l * 2 + 1] = ssq[nt * 2 + 1];
        }
    }
    __syncthreads();
    if (tid < 128) {
        float a = 0.f;
#pragma unroll
        for (int ww = 0; ww < 8; ww++) a += sred[ww * 128 + tid];
        int slot = (blockIdx.x + (blockIdx.y << 2) + blockIdx.z) & 31;
        atomicAdd(&g_stats[slot * 128 + tid], a);
    }

    {
        __half* hdir = g_h + ((bOff + i) * NN + j0) * CMID;
#pragma unroll
        for (int t = 0; t < 8; t++) {
            int flat = t * 128 + wg;
            int row = flat >> 3, c = flat & 7;
            if (j0 + row >= i) {
                uint4 v = *(uint4*)&Dsm[row * 36 + c * 4];
                *(uint4*)&hdir[(size_t)row * CMID + c * 8] = v;
            }
        }
#pragma unroll
        for (int t = 0; t < 8; t++) {
            int row = t * 16 + (wg >> 3), c = wg & 7;
            if (j0 + row > i) {
                uint4 v = *(uint4*)&Dsm[row * 36 + c * 4];
                *(uint4*)&g_h[((bOff + j0 + row) * NN + i) * CMID + c * 8] = v;
            }
        }
    }
}

// ------------------------- K3: BN finalize + scores + softmax -> g_A ------
__global__ __launch_bounds__(256) void k3_softmax(const int* __restrict__ A_init,
                                                  const float* __restrict__ W2,
                                                  const float* __restrict__ b2,
                                                  const float* __restrict__ g1,
                                                  const float* __restrict__ be1) {
    __shared__ float sA[512];
    __shared__ float saf[64], scf[64];
    __shared__ __half2 sa2[32], sc2[32], sw2[32];
    __shared__ float red[16];

    const int tid = threadIdx.x;
    const int i = blockIdx.x, b = blockIdx.y;
    if (tid < 64) {
        float s = 0.f, q = 0.f;
#pragma unroll
        for (int sl = 0; sl < 32; sl++) {
            s += g_stats[sl * 128 + tid];
            q += g_stats[sl * 128 + 64 + tid];
        }
        const float invcnt = 1.0f / (float)((size_t)BB * NN * NN);
        float m = s * invcnt;
        float v = q * invcnt - m * m;
        float a = g1[tid] / sqrtf(v + 1e-5f);
        saf[tid] = a;
        scf[tid] = be1[tid] - m * a;
    }
    __syncthreads();
    if (tid < 32) {
        sa2[tid] = __floats2half2_rn(saf[2 * tid], saf[2 * tid + 1]);
        sc2[tid] = __floats2half2_rn(scf[2 * tid], scf[2 * tid + 1]);
        sw2[tid] = __floats2half2_rn(W2[2 * tid], W2[2 * tid + 1]);
    }
    __syncthreads();

    const int w = tid >> 5, l = tid & 31, g2 = l >> 3, q = l & 7;
    const __half* hrow = g_h + ((size_t)b * NN + i) * NN * CMID;
    const int* arow = A_init + ((size_t)b * NN + i) * NN;
    const float b2v = b2[0];
    __half2 a2[4], c2[4], w2[4];
#pragma unroll
    for (int k = 0; k < 4; k++) {
        a2[k] = sa2[q * 4 + k];
        c2[k] = sc2[q * 4 + k];
        w2[k] = sw2[q * 4 + k];
    }
    const __half2 zero2 = __floats2half2_rn(0.f, 0.f);
    const __half2 leak2 = __floats2half2_rn(0.01f, 0.01f);
    const int o = q * 8;

#pragma unroll 4
    for (int t = 0; t < 16; t++) {
        int j = t * 32 + w * 4 + g2;
        uint4 raw = __ldcs((const uint4*)(hrow + (size_t)j * CMID + o));
        const __half2* hp = (const __half2*)&raw;
        __half2 p2 = zero2;
#pragma unroll
        for (int k = 0; k < 4; k++) {
            __half2 z = __hfma2(hp[k], a2[k], c2[k]);
            __half2 zp = __hmax2(z, zero2);
            __half2 zn = __hmin2(z, zero2);
            z = __hfma2(zn, leak2, zp);
            p2 = __hfma2(z, w2[k], p2);
        }
        float2 pf = __half22float2(p2);
        float p = pf.x + pf.y;
        p += __shfl_down_sync(0xffffffffu, p, 4, 8);
        p += __shfl_down_sync(0xffffffffu, p, 2, 8);
        p += __shfl_down_sync(0xffffffffu, p, 1, 8);
        if (q == 0) sA[j] = (arow[j] > 0) ? (p + b2v) : -9e15f;
    }
    __syncthreads();

    float m0 = fmaxf(sA[tid], sA[tid + 256]);
#pragma unroll
    for (int off = 16; off > 0; off >>= 1) m0 = fmaxf(m0, __shfl_xor_sync(0xffffffffu, m0, off));
    if (l == 0) red[w] = m0;
    __syncthreads();
    float m = red[0];
#pragma unroll
    for (int k = 1; k < 8; k++) m = fmaxf(m, red[k]);

    float e0 = __expf(sA[tid] - m), e1 = __expf(sA[tid + 256] - m);
    float ps = e0 + e1;
#pragma unroll
    for (int off = 16; off > 0; off >>= 1) ps += __shfl_xor_sync(0xffffffffu, ps, off);
    if (l == 0) red[8 + w] = ps;
    __syncthreads();
    float tot = red[8] + red[9] + red[10] + red[11] + red[12] + red[13] + red[14] + red[15];
    float inv = 1.0f / tot;

    const size_t rowbase = ((size_t)b * NN + i) * NN;
    g_A[rowbase + tid]       = e0 * inv;
    g_A[rowbase + 256 + tid] = e1 * inv;
}

// ------------------------- K3b: y0 partials = A[:,js] @ x[js] -------------
__global__ __launch_bounds__(256) void k3b_agg(const float* __restrict__ x) {
    __shared__ float xs[64][128];
    __shared__ float as[32][64];
    const int tid = threadIdx.x;
    const int it = blockIdx.x, js = blockIdx.y, b = blockIdx.z;
    const int i0 = it * 32;
    const int jbase = js * 64;
    const int c = tid & 127, half = tid >> 7;

    for (int idx = tid * 4; idx < 64 * 128; idx += 256 * 4) {
        int r = idx >> 7, cc = idx & 127;
        *(float4*)&xs[r][cc] =
            *(const float4*)&x[((size_t)b * NN + jbase + r) * CIN + cc];
    }
    for (int idx = tid * 4; idx < 32 * 64; idx += 256 * 4) {
        int r = idx >> 6, j = idx & 63;
        *(float4*)&as[r][j] =
            __ldcs((const float4*)&g_A[((size_t)b * NN + i0 + r) * NN + jbase + j]);
    }
    __syncthreads();

    float acc[16];
#pragma unroll
    for (int r = 0; r < 16; r++) acc[r] = 0.f;

    for (int j = 0; j < 64; j += 4) {
        float x0 = xs[j][c], x1 = xs[j + 1][c], x2 = xs[j + 2][c], x3 = xs[j + 3][c];
#pragma unroll
        for (int r = 0; r < 16; r++) {
            float4 a4 = *(const float4*)&as[half * 16 + r][j];
            acc[r] += a4.x * x0 + a4.y * x1 + a4.z * x2 + a4.w * x3;
        }
    }
    float* dst = g_y0p + (size_t)js * BB * NN * CIN;
#pragma unroll
    for (int r = 0; r < 16; r++)
        dst[((size_t)b * NN + i0 + half * 16 + r) * CIN + c] = acc[r];
}

// ------------------------- K4: y1 = y0 @ Wg^T + bg, + BN1d stats ----------
__global__ __launch_bounds__(256) void k4_fc_g(const float* __restrict__ Wg,
                                               const float* __restrict__ bg) {
    __shared__ float ys[16][129];
    __shared__ float s0[128], q0[128];
    const int tid = threadIdx.x;
    const int rb = blockIdx.x;
    const int stride = BB * NN * CIN;
    for (int idx = tid; idx < 16 * 128; idx += 256) {
        int r = idx >> 7, c = idx & 127;
        size_t base = (size_t)(rb * 16 + r) * 128 + c;
        float s = 0.f;
#pragma unroll
        for (int p = 0; p < 8; p++) s += g_y0p[base + (size_t)p * stride];
        ys[r][c] = s;
    }
    __syncthreads();
    const int c = tid & 127, half = tid >> 7;
    float acc[8];
    const float bgv = bg[c];
#pragma unroll
    for (int r = 0; r < 8; r++) acc[r] = bgv;
    const float* wrow = Wg + (size_t)c * 128;
    for (int k = 0; k < 128; k++) {
        float w = __ldg(&wrow[k]);
#pragma unroll
        for (int r = 0; r < 8; r++) acc[r] += ys[half * 8 + r][k] * w;
    }
    float s = 0.f, q = 0.f;
#pragma unroll
    for (int r = 0; r < 8; r++) {
        float v = acc[r];
        s += v; q += v * v;
        g_y1[(size_t)(rb * 16 + half * 8 + r) * 128 + c] = v;
    }
    if (half == 0) { s0[c] = s; q0[c] = q; }
    __syncthreads();
    if (half == 1) {
        atomicAdd(&g_statsg[c], s + s0[c]);
        atomicAdd(&g_statsg[128 + c], q + q0[c]);
    }
}

// ------------------------- K6: BN1d finalize + out GEMM -------------------
__global__ __launch_bounds__(256) void k6_trans(const float* __restrict__ x,
                                                const float* __restrict__ Wt,
                                                const float* __restrict__ bt,
                                                const float* __restrict__ gg,
                                                const float* __restrict__ beg,
                                                float* __restrict__ out) {
    __shared__ float zs[16][257];
    __shared__ float bna[128], bnc[128];
    const int tid = threadIdx.x;
    const int rb = blockIdx.x;
    if (tid < 128) {
        const float invcnt = 1.0f / (float)(BB * NN);
        float m = g_statsg[tid] * invcnt;
        float v = g_statsg[128 + tid] * invcnt - m * m;
        float a = gg[tid] / sqrtf(v + 1e-5f);
        bna[tid] = a;
        bnc[tid] = beg[tid] - m * a;
    }
    __syncthreads();
    for (int idx = tid; idx < 16 * 256; idx += 256) {
        int r = idx >> 8, k = idx & 255;
        int row = rb * 16 + r;
        float v;
        if (k < 128) {
            v = x[(size_t)row * 128 + k];
        } else {
            int hch = k - 128;
            float y = g_y1[(size_t)row * 128 + hch];
            y = y * bna[hch] + bnc[hch];
            v = y > 0.f ? y : 0.01f * y;
        }
        zs[r][k] = v;
    }
    __syncthreads();
    const int c = tid & 127, half = tid >> 7;
    float acc[8];
    const float btv = bt[c];
#pragma unroll
    for (int r = 0; r < 8; r++) acc[r] = btv;
    const float* wrow = Wt + (size_t)c * 256;
    for (int k = 0; k < 256; k++) {
        float w = __ldg(&wrow[k]);
#pragma unroll
        for (int r = 0; r < 8; r++) acc[r] += zs[half * 8 + r][k] * w;
    }
#pragma unroll
    for (int r = 0; r < 8; r++)
        out[(size_t)(rb * 16 + half * 8 + r) * 128 + c] = acc[r];
}

// ------------------------- launch -----------------------------------------
extern "C" void kernel_launch(void* const* d_in, const int* in_sizes, int n_in,
                              void* d_out, int out_size) {
    const float* x      = (const float*)d_in[0];
    const int*   A_init = (const int*)d_in[1];
    const float* W1     = (const float*)d_in[2];
    const float* b1     = (const float*)d_in[3];
    const float* g1     = (const float*)d_in[4];
    const float* be1    = (const float*)d_in[5];
    const float* W2     = (const float*)d_in[6];
    const float* b2     = (const float*)d_in[7];
    const float* Wg     = (const float*)d_in[8];
    const float* bg     = (const float*)d_in[9];
    const float* gg     = (const float*)d_in[10];
    const float* beg    = (const float*)d_in[11];
    const float* Wt     = (const float*)d_in[12];
    const float* bt     = (const float*)d_in[13];
    float* out = (float*)d_out;

    cudaFuncSetAttribute(k1_pair_gemm, cudaFuncAttributeMaxDynamicSharedMemorySize, K1_SMEM);

    k_init<<<640, 256>>>(x, W1, b1);
    dim3 g1grid(4, 256, 4);
    k1_pair_gemm<<<g1grid, 256, K1_SMEM>>>();
    dim3 g3grid(512, 4);
    k3_softmax<<<g3grid, 256>>>(A_init, W2, b2, g1, be1);
    dim3 g3bgrid(16, 8, 4);
    k3b_agg<<<g3bgrid, 256>>>(x);
    k4_fc_g<<<128, 256>>>(Wg, bg);
    k6_trans<<<128, 256>>>(x, Wt, bt, gg, beg, out);
}

// round 16
// speedup vs baseline: 1.5274x; 1.0825x over previous
#include <cuda_runtime.h>
#include <cuda_fp16.h>
#include <math.h>
#include <cstdint>

#define BB   4
#define NN   512
#define CIN  128
#define CMID 64

// ------------------------- scratch (device globals) ------------------------
__device__ __half g_h[(size_t)BB * NN * NN * CMID];  // 128 MB h (fp16)
__device__ float g_A[(size_t)BB * NN * NN];          // 4 MB softmax probs
__device__ float g_u[BB * NN * CMID];                // u = x@W1^T + b1/2 (fp32 exact)
__device__ __half g_x16[BB * NN * CIN];              // fp16 copy of x
__device__ uint32_t g_whi[64 * 64];                  // W1 fp16x2 [o][kp]
__device__ float g_stats[32 * 128];
__device__ float g_y0p[16 * BB * NN * CIN];          // y0 partials (16 j-slices)
__device__ float g_y1[BB * NN * 128];
__device__ float g_statsg[2 * 128];

// ------------------------- PTX helpers -------------------------------------
__device__ __forceinline__ void mma_f16(float* d, const uint32_t* a,
                                        uint32_t b0, uint32_t b1) {
    asm volatile(
        "mma.sync.aligned.m16n8k16.row.col.f32.f16.f16.f32 "
        "{%0,%1,%2,%3}, {%4,%5,%6,%7}, {%8,%9}, {%0,%1,%2,%3};"
        : "+f"(d[0]), "+f"(d[1]), "+f"(d[2]), "+f"(d[3])
        : "r"(a[0]), "r"(a[1]), "r"(a[2]), "r"(a[3]), "r"(b0), "r"(b1));
}
__device__ __forceinline__ void ldsm_x4(uint32_t &r0, uint32_t &r1,
                                        uint32_t &r2, uint32_t &r3, uint32_t addr) {
    asm volatile("ldmatrix.sync.aligned.m8n8.x4.shared.b16 {%0,%1,%2,%3}, [%4];"
                 : "=r"(r0), "=r"(r1), "=r"(r2), "=r"(r3) : "r"(addr));
}
__device__ __forceinline__ uint32_t hmin2u(uint32_t a, uint32_t b) {
    __half2 r = __hmin2(*reinterpret_cast<__half2*>(&a), *reinterpret_cast<__half2*>(&b));
    return *reinterpret_cast<uint32_t*>(&r);
}

// ------------------------- Kinit: cvt + W fp16 + u-GEMM + zero stats ------
__global__ __launch_bounds__(256) void k_init(const float* __restrict__ x,
                                              const float* __restrict__ W1,
                                              const float* __restrict__ b1) {
    __shared__ float xr[16][128];
    __shared__ float Ws[128 * 64];
    const int tid = threadIdx.x;
    const int blk = blockIdx.x;

    if (blk < 512) {
        int idx = blk * 256 + tid;
        float2 v = *(const float2*)&x[idx * 2];
        uint32_t p;
        asm("cvt.rn.f16x2.f32 %0, %1, %2;" : "=r"(p) : "f"(v.y), "f"(v.x));
        ((uint32_t*)g_x16)[idx] = p;

        if (blk < 16) {
            int i2 = blk * 256 + tid;
            float2 wv = *(const float2*)&W1[i2 * 2];
            uint32_t hp;
            asm("cvt.rn.f16x2.f32 %0, %1, %2;" : "=r"(hp) : "f"(wv.y), "f"(wv.x));
            g_whi[i2] = hp;
        }
        if (blk == 511) {
            for (int i = tid; i < 32 * 128; i += 256) g_stats[i] = 0.f;
            g_statsg[tid] = 0.f;
        }
        return;
    }

    const int r0 = (blk - 512) * 16;
    for (int idx = tid; idx < 64 * 128; idx += 256)
        Ws[(idx & 127) * 64 + (idx >> 7)] = W1[idx];
    for (int idx = tid; idx < 16 * 128; idx += 256)
        xr[idx >> 7][idx & 127] = x[(size_t)(r0 + (idx >> 7)) * 128 + (idx & 127)];
    __syncthreads();
    const int row = tid >> 4, chg = (tid & 15) * 4;
    float acc[4];
#pragma unroll
    for (int c = 0; c < 4; c++) acc[c] = 0.5f * b1[chg + c];
    for (int k = 0; k < 128; k++) {
        float xv = xr[row][k];
#pragma unroll
        for (int c = 0; c < 4; c++) acc[c] += Ws[k * 64 + chg + c] * xv;
    }
#pragma unroll
    for (int c = 0; c < 4; c++)
        g_u[(size_t)(r0 + row) * CMID + chg + c] = acc[c];
}

// ------------------------- K1: symmetric pairwise GEMM (2 i / block) ------
// h = u_i + u_j - 2*(min16(xi,xj) @ W16^T); single W term (residual dropped).
#define OFF_XIP  0
#define OFF_SRED 512
#define OFF_XJ   4608                   // 128*68 u32 = 34816B (D0 tile after)
#define OFF_WHI  39424                  // 64*68 u32 region, padded to 18560B for D1
#define K1_SMEM  57984

__global__ __launch_bounds__(256) void k1_pair_gemm() {
    const int jt = blockIdx.x, iy = blockIdx.y, b = blockIdx.z;
    const int i0 = iy * 2;
    if (jt < (i0 >> 7)) return;

    extern __shared__ char smem[];
    uint32_t* xiP  = (uint32_t*)(smem + OFF_XIP);
    float*    sred = (float*)(smem + OFF_SRED);
    uint32_t* xjs  = (uint32_t*)(smem + OFF_XJ);
    uint32_t* whiS = (uint32_t*)(smem + OFF_WHI);

    const uint32_t sb = (uint32_t)__cvta_generic_to_shared(smem);
    const uint32_t xj_b  = sb + OFF_XJ;
    const uint32_t whi_b = sb + OFF_WHI;

    const int tid = threadIdx.x;
    const int hf = tid >> 7;
    const int wg = tid & 127;
    const int w = wg >> 5, l = wg & 31;
    const int lr = l >> 2, lc = l & 3;
    const int i = i0 + hf;
    const int j0 = jt * 128;
    const size_t bOff = (size_t)b * NN;
    const uint32_t* x16u = (const uint32_t*)g_x16;

    if (tid < 128) xiP[tid] = x16u[(bOff + i0 + (tid >> 6)) * 64 + (tid & 63)];
    for (int idx = tid; idx < 128 * 64; idx += 256) {
        int row = idx >> 6, col = idx & 63;
        xjs[row * 68 + col] = x16u[(bOff + j0 + row) * 64 + col];
    }
    for (int idx = tid; idx < 64 * 64; idx += 256) {
        int o = idx >> 6, kp = idx & 63;
        whiS[o * 68 + kp] = g_whi[idx];
    }
    __syncthreads();

    uint32_t xvlo[8], xvhi[8];
#pragma unroll
    for (int s = 0; s < 8; s++) {
        xvlo[s] = xiP[hf * 64 + s * 8 + lc];
        xvhi[s] = xiP[hf * 64 + s * 8 + 4 + lc];
    }

    uint32_t ofsA[2], ofsW[4];
#pragma unroll
    for (int mt = 0; mt < 2; mt++) {
        int rowA = w * 32 + mt * 16 + (l & 15);
        ofsA[mt] = (uint32_t)((rowA * 68 + ((l >> 4) << 2)) * 4);
    }
#pragma unroll
    for (int q = 0; q < 4; q++) {
        int rowW = 16 * q + ((l >> 4) << 3) + (l & 7);
        int woff = ((l >> 3) & 1) << 2;
        ofsW[q] = (uint32_t)((rowW * 68 + woff) * 4);
    }

    float d[2][8][4];
#pragma unroll
    for (int mt = 0; mt < 2; mt++)
#pragma unroll
        for (int nt = 0; nt < 8; nt++)
#pragma unroll
            for (int r = 0; r < 4; r++) d[mt][nt][r] = 0.f;

#pragma unroll
    for (int s = 0; s < 8; s++) {
        const uint32_t kb = (uint32_t)(s * 32);
        uint32_t a[2][4];
#pragma unroll
        for (int mt = 0; mt < 2; mt++) {
            uint32_t r0, r1, r2, r3;
            ldsm_x4(r0, r1, r2, r3, xj_b + ofsA[mt] + kb);
            a[mt][0] = hmin2u(r0, xvlo[s]);
            a[mt][1] = hmin2u(r1, xvlo[s]);
            a[mt][2] = hmin2u(r2, xvhi[s]);
            a[mt][3] = hmin2u(r3, xvhi[s]);
        }
#pragma unroll
        for (int q = 0; q < 4; q++) {
            uint32_t h0, h1, h2, h3;
            ldsm_x4(h0, h1, h2, h3, whi_b + ofsW[q] + kb);
            mma_f16(d[0][2 * q],     a[0], h0, h1);
            mma_f16(d[0][2 * q + 1], a[0], h2, h3);
            mma_f16(d[1][2 * q],     a[1], h0, h1);
            mma_f16(d[1][2 * q + 1], a[1], h2, h3);
        }
    }
    __syncthreads();   // tiles dead; reuse as D tiles (pitch 36 words)

    uint32_t* Dsm = (hf == 0) ? xjs : whiS;
    float ssum[16], ssq[16];
#pragma unroll
    for (int s = 0; s < 16; s++) { ssum[s] = 0.f; ssq[s] = 0.f; }

    const float* uB = g_u + bOff * CMID;
    float uI[16];
#pragma unroll
    for (int nt = 0; nt < 8; nt++) {
        float2 t = *(const float2*)&uB[(size_t)i * CMID + nt * 8 + lc * 2];
        uI[nt * 2] = t.x; uI[nt * 2 + 1] = t.y;
    }

#pragma unroll
    for (int mt = 0; mt < 2; mt++) {
        const int row0 = w * 32 + mt * 16 + lr;
        const int row1 = row0 + 8;
        const int jrow0 = j0 + row0, jrow1 = j0 + row1;
        const float w0f = (jrow0 > i) ? 2.f : (jrow0 == i ? 1.f : 0.f);
        const float w1f = (jrow1 > i) ? 2.f : (jrow1 == i ? 1.f : 0.f);
        const float* uj0p = &uB[(size_t)jrow0 * CMID];
        const float* uj1p = &uB[(size_t)jrow1 * CMID];
#pragma unroll
        for (int nt = 0; nt < 8; nt++) {
            const int ch = nt * 8 + lc * 2;
            float2 uj0 = *(const float2*)&uj0p[ch];
            float2 uj1 = *(const float2*)&uj1p[ch];
            float v0 = uI[nt * 2]     + uj0.x - 2.f * d[mt][nt][0];
            float v1 = uI[nt * 2 + 1] + uj0.y - 2.f * d[mt][nt][1];
            float v2 = uI[nt * 2]     + uj1.x - 2.f * d[mt][nt][2];
            float v3 = uI[nt * 2 + 1] + uj1.y - 2.f * d[mt][nt][3];
            uint32_t p01, p23;
            asm("cvt.rn.f16x2.f32 %0, %1, %2;" : "=r"(p01) : "f"(v1), "f"(v0));
            asm("cvt.rn.f16x2.f32 %0, %1, %2;" : "=r"(p23) : "f"(v3), "f"(v2));
            Dsm[row0 * 36 + nt * 4 + lc] = p01;
            Dsm[row1 * 36 + nt * 4 + lc] = p23;
            ssum[nt * 2]     += w0f * v0 + w1f * v2;
            ssq[nt * 2]      += w0f * v0 * v0 + w1f * v2 * v2;
            ssum[nt * 2 + 1] += w0f * v1 + w1f * v3;
            ssq[nt * 2 + 1]  += w0f * v1 * v1 + w1f * v3 * v3;
        }
    }
#pragma unroll
    for (int s = 0; s < 16; s++) {
#pragma unroll
        for (int off = 4; off <= 16; off <<= 1) {
            ssum[s] += __shfl_xor_sync(0xffffffffu, ssum[s], off);
            ssq[s]  += __shfl_xor_sync(0xffffffffu, ssq[s], off);
        }
    }
    const int warp8 = tid >> 5;
    if (l < 4) {
#pragma unroll
        for (int nt = 0; nt < 8; nt++) {
            sred[warp8 * 128 + nt * 8 + l * 2]          = ssum[nt * 2];
            sred[warp8 * 128 + nt * 8 + l * 2 + 1]      = ssum[nt * 2 + 1];
            sred[warp8 * 128 + 64 + nt * 8 + l * 2]     = ssq[nt * 2];
            sred[warp8 * 128 + 64 + nt * 8 + l * 2 + 1] = ssq[nt * 2 + 1];
        }
    }
    __syncthreads();
    if (tid < 128) {
        float a = 0.f;
#pragma unroll
        for (int ww = 0; ww < 8; ww++) a += sred[ww * 128 + tid];
        int slot = (blockIdx.x + (blockIdx.y << 2) + blockIdx.z) & 31;
        atomicAdd(&g_stats[slot * 128 + tid], a);
    }

    {
        __half* hdir = g_h + ((bOff + i) * NN + j0) * CMID;
#pragma unroll
        for (int t = 0; t < 8; t++) {
            int flat = t * 128 + wg;
            int row = flat >> 3, c = flat & 7;
            if (j0 + row >= i) {
                uint4 v = *(uint4*)&Dsm[row * 36 + c * 4];
                *(uint4*)&hdir[(size_t)row * CMID + c * 8] = v;
            }
        }
#pragma unroll
        for (int t = 0; t < 8; t++) {
            int row = t * 16 + (wg >> 3), c = wg & 7;
            if (j0 + row > i) {
                uint4 v = *(uint4*)&Dsm[row * 36 + c * 4];
                *(uint4*)&g_h[((bOff + j0 + row) * NN + i) * CMID + c * 8] = v;
            }
        }
    }
}

// ------------------------- K3: BN finalize + scores + softmax -> g_A ------
__global__ __launch_bounds__(256) void k3_softmax(const int* __restrict__ A_init,
                                                  const float* __restrict__ W2,
                                                  const float* __restrict__ b2,
                                                  const float* __restrict__ g1,
                                                  const float* __restrict__ be1) {
    __shared__ float sA[512];
    __shared__ float saf[64], scf[64];
    __shared__ __half2 sa2[32], sc2[32], sw2[32];
    __shared__ float red[16];

    const int tid = threadIdx.x;
    const int i = blockIdx.x, b = blockIdx.y;
    if (tid < 64) {
        float s = 0.f, q = 0.f;
#pragma unroll
        for (int sl = 0; sl < 32; sl++) {
            s += g_stats[sl * 128 + tid];
            q += g_stats[sl * 128 + 64 + tid];
        }
        const float invcnt = 1.0f / (float)((size_t)BB * NN * NN);
        float m = s * invcnt;
        float v = q * invcnt - m * m;
        float a = g1[tid] / sqrtf(v + 1e-5f);
        saf[tid] = a;
        scf[tid] = be1[tid] - m * a;
    }
    __syncthreads();
    if (tid < 32) {
        sa2[tid] = __floats2half2_rn(saf[2 * tid], saf[2 * tid + 1]);
        sc2[tid] = __floats2half2_rn(scf[2 * tid], scf[2 * tid + 1]);
        sw2[tid] = __floats2half2_rn(W2[2 * tid], W2[2 * tid + 1]);
    }
    __syncthreads();

    const int w = tid >> 5, l = tid & 31, g2 = l >> 3, q = l & 7;
    const __half* hrow = g_h + ((size_t)b * NN + i) * NN * CMID;
    const int* arow = A_init + ((size_t)b * NN + i) * NN;
    const float b2v = b2[0];
    __half2 a2[4], c2[4], w2[4];
#pragma unroll
    for (int k = 0; k < 4; k++) {
        a2[k] = sa2[q * 4 + k];
        c2[k] = sc2[q * 4 + k];
        w2[k] = sw2[q * 4 + k];
    }
    const __half2 zero2 = __floats2half2_rn(0.f, 0.f);
    const __half2 leak2 = __floats2half2_rn(0.01f, 0.01f);
    const int o = q * 8;

#pragma unroll 4
    for (int t = 0; t < 16; t++) {
        int j = t * 32 + w * 4 + g2;
        uint4 raw = __ldcs((const uint4*)(hrow + (size_t)j * CMID + o));
        const __half2* hp = (const __half2*)&raw;
        __half2 p2 = zero2;
#pragma unroll
        for (int k = 0; k < 4; k++) {
            __half2 z = __hfma2(hp[k], a2[k], c2[k]);
            __half2 zp = __hmax2(z, zero2);
            __half2 zn = __hmin2(z, zero2);
            z = __hfma2(zn, leak2, zp);
            p2 = __hfma2(z, w2[k], p2);
        }
        float2 pf = __half22float2(p2);
        float p = pf.x + pf.y;
        p += __shfl_down_sync(0xffffffffu, p, 4, 8);
        p += __shfl_down_sync(0xffffffffu, p, 2, 8);
        p += __shfl_down_sync(0xffffffffu, p, 1, 8);
        if (q == 0) sA[j] = (arow[j] > 0) ? (p + b2v) : -9e15f;
    }
    __syncthreads();

    float m0 = fmaxf(sA[tid], sA[tid + 256]);
#pragma unroll
    for (int off = 16; off > 0; off >>= 1) m0 = fmaxf(m0, __shfl_xor_sync(0xffffffffu, m0, off));
    if (l == 0) red[w] = m0;
    __syncthreads();
    float m = red[0];
#pragma unroll
    for (int k = 1; k < 8; k++) m = fmaxf(m, red[k]);

    float e0 = __expf(sA[tid] - m), e1 = __expf(sA[tid + 256] - m);
    float ps = e0 + e1;
#pragma unroll
    for (int off = 16; off > 0; off >>= 1) ps += __shfl_xor_sync(0xffffffffu, ps, off);
    if (l == 0) red[8 + w] = ps;
    __syncthreads();
    float tot = red[8] + red[9] + red[10] + red[11] + red[12] + red[13] + red[14] + red[15];
    float inv = 1.0f / tot;

    const size_t rowbase = ((size_t)b * NN + i) * NN;
    g_A[rowbase + tid]       = e0 * inv;
    g_A[rowbase + 256 + tid] = e1 * inv;
}

// ------------------------- K3b: y0 partials = A[:,js] @ x[js] -------------
// grid (16 it, 16 js, 4 b), 256 threads; block = 32 i x 128 ch x 32 j's.
__global__ __launch_bounds__(256) void k3b_agg(const float* __restrict__ x) {
    __shared__ float xs[32][128];
    __shared__ float as[32][32];
    const int tid = threadIdx.x;
    const int it = blockIdx.x, js = blockIdx.y, b = blockIdx.z;
    const int i0 = it * 32;
    const int jbase = js * 32;
    const int c = tid & 127, half = tid >> 7;

    for (int idx = tid * 4; idx < 32 * 128; idx += 256 * 4) {
        int r = idx >> 7, cc = idx & 127;
        *(float4*)&xs[r][cc] =
            *(const float4*)&x[((size_t)b * NN + jbase + r) * CIN + cc];
    }
    {
        int idx = tid * 4;              // covers 32*32 = 1024 floats
        int r = idx >> 5, j = idx & 31;
        *(float4*)&as[r][j] =
            __ldcs((const float4*)&g_A[((size_t)b * NN + i0 + r) * NN + jbase + j]);
    }
    __syncthreads();

    float acc[16];
#pragma unroll
    for (int r = 0; r < 16; r++) acc[r] = 0.f;

#pragma unroll
    for (int j = 0; j < 32; j += 4) {
        float x0 = xs[j][c], x1 = xs[j + 1][c], x2 = xs[j + 2][c], x3 = xs[j + 3][c];
#pragma unroll
        for (int r = 0; r < 16; r++) {
            float4 a4 = *(const float4*)&as[half * 16 + r][j];
            acc[r] += a4.x * x0 + a4.y * x1 + a4.z * x2 + a4.w * x3;
        }
    }
    float* dst = g_y0p + (size_t)js * BB * NN * CIN;
#pragma unroll
    for (int r = 0; r < 16; r++)
        dst[((size_t)b * NN + i0 + half * 16 + r) * CIN + c] = acc[r];
}

// ------------------------- K4: y1 = y0 @ Wg^T + bg, + BN1d stats ----------
__global__ __launch_bounds__(256) void k4_fc_g(const float* __restrict__ Wg,
                                               const float* __restrict__ bg) {
    __shared__ float ys[16][129];
    __shared__ float s0[128], q0[128];
    const int tid = threadIdx.x;
    const int rb = blockIdx.x;
    const int stride = BB * NN * CIN;
    for (int idx = tid; idx < 16 * 128; idx += 256) {
        int r = idx >> 7, c = idx & 127;
        size_t base = (size_t)(rb * 16 + r) * 128 + c;
        float s = 0.f;
#pragma unroll
        for (int p = 0; p < 16; p++) s += g_y0p[base + (size_t)p * stride];
        ys[r][c] = s;
    }
    __syncthreads();
    const int c = tid & 127, half = tid >> 7;
    float acc[8];
    const float bgv = bg[c];
#pragma unroll
    for (int r = 0; r < 8; r++) acc[r] = bgv;
    const float* wrow = Wg + (size_t)c * 128;
    for (int k = 0; k < 128; k++) {
        float w = __ldg(&wrow[k]);
#pragma unroll
        for (int r = 0; r < 8; r++) acc[r] += ys[half * 8 + r][k] * w;
    }
    float s = 0.f, q = 0.f;
#pragma unroll
    for (int r = 0; r < 8; r++) {
        float v = acc[r];
        s += v; q += v * v;
        g_y1[(size_t)(rb * 16 + half * 8 + r) * 128 + c] = v;
    }
    if (half == 0) { s0[c] = s; q0[c] = q; }
    __syncthreads();
    if (half == 1) {
        atomicAdd(&g_statsg[c], s + s0[c]);
        atomicAdd(&g_statsg[128 + c], q + q0[c]);
    }
}

// ------------------------- K6: BN1d finalize + out GEMM -------------------
__global__ __launch_bounds__(256) void k6_trans(const float* __restrict__ x,
                                                const float* __restrict__ Wt,
                                                const float* __restrict__ bt,
                                                const float* __restrict__ gg,
                                                const float* __restrict__ beg,
                                                float* __restrict__ out) {
    __shared__ float zs[16][257];
    __shared__ float bna[128], bnc[128];
    const int tid = threadIdx.x;
    const int rb = blockIdx.x;
    if (tid < 128) {
        const float invcnt = 1.0f / (float)(BB * NN);
        float m = g_statsg[tid] * invcnt;
        float v = g_statsg[128 + tid] * invcnt - m * m;
        float a = gg[tid] / sqrtf(v + 1e-5f);
        bna[tid] = a;
        bnc[tid] = beg[tid] - m * a;
    }
    __syncthreads();
    for (int idx = tid; idx < 16 * 256; idx += 256) {
        int r = idx >> 8, k = idx & 255;
        int row = rb * 16 + r;
        float v;
        if (k < 128) {
            v = x[(size_t)row * 128 + k];
        } else {
            int hch = k - 128;
            float y = g_y1[(size_t)row * 128 + hch];
            y = y * bna[hch] + bnc[hch];
            v = y > 0.f ? y : 0.01f * y;
        }
        zs[r][k] = v;
    }
    __syncthreads();
    const int c = tid & 127, half = tid >> 7;
    float acc[8];
    const float btv = bt[c];
#pragma unroll
    for (int r = 0; r < 8; r++) acc[r] = btv;
    const float* wrow = Wt + (size_t)c * 256;
    for (int k = 0; k < 256; k++) {
        float w = __ldg(&wrow[k]);
#pragma unroll
        for (int r = 0; r < 8; r++) acc[r] += zs[half * 8 + r][k] * w;
    }
#pragma unroll
    for (int r = 0; r < 8; r++)
        out[(size_t)(rb * 16 + half * 8 + r) * 128 + c] = acc[r];
}

// ------------------------- launch -----------------------------------------
extern "C" void kernel_launch(void* const* d_in, const int* in_sizes, int n_in,
                              void* d_out, int out_size) {
    const float* x      = (const float*)d_in[0];
    const int*   A_init = (const int*)d_in[1];
    const float* W1     = (const float*)d_in[2];
    const float* b1     = (const float*)d_in[3];
    const float* g1     = (const float*)d_in[4];
    const float* be1    = (const float*)d_in[5];
    const float* W2     = (const float*)d_in[6];
    const float* b2     = (const float*)d_in[7];
    const float* Wg     = (const float*)d_in[8];
    const float* bg     = (const float*)d_in[9];
    const float* gg     = (const float*)d_in[10];
    const float* beg    = (const float*)d_in[11];
    const float* Wt     = (const float*)d_in[12];
    const float* bt     = (const float*)d_in[13];
    float* out = (float*)d_out;

    cudaFuncSetAttribute(k1_pair_gemm, cudaFuncAttributeMaxDynamicSharedMemorySize, K1_SMEM);

    k_init<<<640, 256>>>(x, W1, b1);
    dim3 g1grid(4, 256, 4);
    k1_pair_gemm<<<g1grid, 256, K1_SMEM>>>();
    dim3 g3grid(512, 4);
    k3_softmax<<<g3grid, 256>>>(A_init, W2, b2, g1, be1);
    dim3 g3bgrid(16, 16, 4);
    k3b_agg<<<g3bgrid, 256>>>(x);
    k4_fc_g<<<128, 256>>>(Wg, bg);
    k6_trans<<<128, 256>>>(x, Wt, bt, gg, beg, out);
}